// round 5
// baseline (speedup 1.0000x reference)
#include <cuda_runtime.h>
#include <cuda_fp16.h>

#define NN 50000
#define NE 500000

typedef unsigned long long u64;

// ---- persistent device scratch ----
__device__ __half g_WsgH[64 * 256];   // W_src @ W_gate, fp16, PERMUTED columns
__device__ __half g_WdgH[64 * 256];   // W_dst @ W_gate, fp16, PERMUTED columns
__device__ __half g_Wg8h[8 * 256];    // W_enc @ W_gate, packed half2 [(k*4+j)*32+l]
__device__ float  g_bgf[256];         // fused bias, float2 layout [(j*32+l)]
__device__ __half g_GsP[NN * 256];    // gate-pre (src side), interleaved per-lane chunks
__device__ __half g_GdP[NN * 256];    // gate-pre (dst side)
__device__ __half g_zP[NN * 256];     // packed z: per lane l: [z1x(2l..),z1y..,z1z..,z0..]
__device__ float  g_accP[NN * 256];   // interleaved acc: lane l: [s0,s1,vx0,vx1,vy0,vy1,vz0,vz1]

// ---- packed f32x2 helpers ----
__device__ __forceinline__ u64 pk(float x, float y) {
    u64 r; asm("mov.b64 %0,{%1,%2};" : "=l"(r) : "f"(x), "f"(y)); return r;
}
__device__ __forceinline__ float2 upk(u64 v) {
    float2 f; asm("mov.b64 {%0,%1},%2;" : "=f"(f.x), "=f"(f.y) : "l"(v)); return f;
}
__device__ __forceinline__ u64 ffma2(u64 a, u64 b, u64 c) {
    u64 r; asm("fma.rn.f32x2 %0,%1,%2,%3;" : "=l"(r) : "l"(a), "l"(b), "l"(c)); return r;
}
__device__ __forceinline__ u64 fmul2(u64 a, u64 b) {
    u64 r; asm("mul.rn.f32x2 %0,%1,%2;" : "=l"(r) : "l"(a), "l"(b)); return r;
}
__device__ __forceinline__ u64 h2f(__half2 h) {
    float2 f = __half22float2(h); return pk(f.x, f.y);
}
__device__ __forceinline__ void red4(float* p, u64 ab, u64 cd) {
    float2 a = upk(ab), c = upk(cd);
    asm volatile("red.global.add.v4.f32 [%0], {%1,%2,%3,%4};"
                 :: "l"(p), "f"(a.x), "f"(a.y), "f"(c.x), "f"(c.y) : "memory");
}

// ---------------------------------------------------------------------------
// 1) fold weights, with layout permutations baked in
//    interleaved channel index c' = l*8 + j*2 + h  <->  c = j*64 + 2l + h
// ---------------------------------------------------------------------------
__global__ void prep_weights(const float* __restrict__ W_src, const float* __restrict__ W_dst,
                             const float* __restrict__ W_enc, const float* __restrict__ W_gate,
                             const float* __restrict__ b_gate, const float* __restrict__ b_enc,
                             const float* __restrict__ b_src, const float* __restrict__ b_dst) {
    int idx = blockIdx.x * blockDim.x + threadIdx.x;
    if (idx < 16384) {
        int k = idx >> 8, cp = idx & 255;
        int l = cp >> 3, j = (cp >> 1) & 3, h = cp & 1;
        int c = j * 64 + 2 * l + h;
        float s = 0.f;
        #pragma unroll 8
        for (int t = 0; t < 64; t++) s += W_src[k * 64 + t] * W_gate[t * 256 + c];
        g_WsgH[idx] = __float2half(s);
    } else if (idx < 32768) {
        int t0 = idx - 16384;
        int k = t0 >> 8, cp = t0 & 255;
        int l = cp >> 3, j = (cp >> 1) & 3, h = cp & 1;
        int c = j * 64 + 2 * l + h;
        float s = 0.f;
        #pragma unroll 8
        for (int t = 0; t < 64; t++) s += W_dst[k * 64 + t] * W_gate[t * 256 + c];
        g_WdgH[t0] = __float2half(s);
    } else if (idx < 34816) {
        int t0 = idx - 32768;
        int k = t0 >> 8, c = t0 & 255;   // c = source channel
        float s = 0.f;
        #pragma unroll 8
        for (int t = 0; t < 64; t++) s += W_enc[k * 64 + t] * W_gate[t * 256 + c];
        int j = c >> 6, l = (c & 63) >> 1, h = c & 1;
        g_Wg8h[((k * 4 + j) * 32 + l) * 2 + h] = __float2half(s);
    } else if (idx < 35072) {
        int c = idx - 34816;
        float s = b_gate[c];
        for (int t = 0; t < 64; t++) s += (b_enc[t] + b_src[t] + b_dst[t]) * W_gate[t * 256 + c];
        int j = c >> 6, l = (c & 63) >> 1, h = c & 1;
        g_bgf[(j * 32 + l) * 2 + h] = s;
    }
}

// ---------------------------------------------------------------------------
// 2) node precompute: Gs/Gd = emb @ (permuted fp16 weights), 32 nodes/block,
//    packed f32x2 accumulation over node pairs.
// ---------------------------------------------------------------------------
__global__ __launch_bounds__(512) void node_pre(const float* __restrict__ emb) {
    __shared__ float esT[64][36];   // transposed emb tile; 36 floats/row = 144B (8B-aligned)
    int base = blockIdx.x * 32;
    for (int i = threadIdx.x; i < 32 * 64; i += 512) {
        int n = i >> 6, c = i & 63;
        esT[c][n] = (base + n < NN) ? emb[(base + n) * 64 + c] : 0.f;
    }
    __syncthreads();
    int t = threadIdx.x;
    int cp = t & 255;
    const __half* W = (t < 256) ? g_WsgH : g_WdgH;
    __half* G = (t < 256) ? g_GsP : g_GdP;
    u64 a[16];
    #pragma unroll
    for (int p = 0; p < 16; p++) a[p] = 0ULL;
    for (int k = 0; k < 64; k++) {
        float wv = __half2float(W[k * 256 + cp]);
        u64 w2 = pk(wv, wv);
        const u64* row = (const u64*)&esT[k][0];
        #pragma unroll
        for (int p = 0; p < 16; p++) a[p] = ffma2(w2, row[p], a[p]);
    }
    #pragma unroll
    for (int p = 0; p < 16; p++) {
        float2 v = upk(a[p]);
        int n0 = base + 2 * p;
        if (n0 < NN)     G[(size_t)n0 * 256 + cp]       = __float2half(v.x);
        if (n0 + 1 < NN) G[(size_t)(n0 + 1) * 256 + cp] = __float2half(v.y);
    }
}

// ---------------------------------------------------------------------------
// 3) fused: zero acc + pack z0/z1 into per-lane 16B chunks
// ---------------------------------------------------------------------------
__global__ void zero_convert(const float* __restrict__ z0, const float* __restrict__ z1) {
    const int T0 = NN * 64;            // float4 zeroes for acc
    const int T1 = T0 + NN * 128;      // half2 packs for z
    int i = blockIdx.x * blockDim.x + threadIdx.x;
    int stride = gridDim.x * blockDim.x;
    for (; i < T1; i += stride) {
        if (i < T0) {
            ((float4*)g_accP)[i] = make_float4(0.f, 0.f, 0.f, 0.f);
        } else {
            int j = i - T0;
            int n = j >> 7, p = j & 127;
            int t = p >> 5, l = p & 31;
            float2 v = (t < 3) ? ((const float2*)z1)[n * 96 + t * 32 + l]
                               : ((const float2*)z0)[n * 32 + l];
            ((__half2*)g_zP)[n * 128 + l * 4 + t] = __float22half2_rn(v);
        }
    }
}

// ---------------------------------------------------------------------------
// 4) edge kernel: 3 LDG.128 gathers + 2 REDG.v4 per lane per edge,
//    packed f32x2 gate + message math.
// ---------------------------------------------------------------------------
__global__ __launch_bounds__(256) void edge_kernel(const int* __restrict__ src,
                                                   const int* __restrict__ dst,
                                                   const float* __restrict__ r_ij) {
    const int lane = threadIdx.x & 31;
    const int warp = blockIdx.x * (blockDim.x >> 5) + (threadIdx.x >> 5);
    const int nwarp = gridDim.x * (blockDim.x >> 5);

    // per-lane weights: w[j][k] = f32x2 pair for channels (2l, 2l+1)
    u64 w[4][8];
    float2 bgj[4];
    {
        const __half2* Wp = (const __half2*)g_Wg8h;
        const float2* bp = (const float2*)g_bgf;
        #pragma unroll
        for (int j = 0; j < 4; j++) {
            bgj[j] = bp[j * 32 + lane];
            #pragma unroll
            for (int k = 0; k < 8; k++) w[j][k] = h2f(Wp[(k * 4 + j) * 32 + lane]);
        }
    }

    int e = warp;
    int s = 0, d = 0;
    if (e < NE) { s = __ldg(src + e); d = __ldg(dst + e); }
    while (e < NE) {
        // gathers (interleaved fp16 layouts, one LDG.128 each)
        uint4 gsv = __ldg((const uint4*)(g_GsP + (size_t)s * 256 + lane * 8));
        uint4 gdv = __ldg((const uint4*)(g_GdP + (size_t)d * 256 + lane * 8));
        uint4 zv  = __ldg((const uint4*)(g_zP  + (size_t)d * 256 + lane * 8));
        float rx = __ldg(r_ij + 3 * e), ry = __ldg(r_ij + 3 * e + 1), rz = __ldg(r_ij + 3 * e + 2);

        // prefetch next edge indices
        int en = e + nwarp, sn = s, dn = d;
        if (en < NE) { sn = __ldg(src + en); dn = __ldg(dst + en); }

        float d2 = fmaf(rx, rx, fmaf(ry, ry, rz * rz));
        float dd = sqrtf(d2);
        float inv = rsqrtf(fmaf(12.25f, d2, 1.f));
        float hx = 3.5f * rx * inv, hy = 3.5f * ry * inv, hz = 3.5f * rz * inv;

        // gate = Gs + Gd + bias + rbf @ Wg8  (packed f32x2)
        const __half2* gs2 = (const __half2*)&gsv;
        const __half2* gd2 = (const __half2*)&gdv;
        u64 g[4];
        #pragma unroll
        for (int j = 0; j < 4; j++) {
            float2 a = __half22float2(gs2[j]);
            float2 b = __half22float2(gd2[j]);
            g[j] = pk(a.x + b.x + bgj[j].x, a.y + b.y + bgj[j].y);
        }
        #pragma unroll
        for (int k = 0; k < 8; k++) {
            float u = fmaf(dd, 4.f, -(8.f / 7.f) * (float)k);
            float ee = __expf(-u * u);
            u64 r2 = pk(ee, ee);
            #pragma unroll
            for (int j = 0; j < 4; j++) g[j] = ffma2(r2, w[j][k], g[j]);
        }

        const __half2* zh = (const __half2*)&zv;
        u64 ZA = h2f(zh[0]), ZB = h2f(zh[1]), ZC = h2f(zh[2]), Z0 = h2f(zh[3]);
        u64 HX = pk(hx, hx), HY = pk(hy, hy), HZ = pk(hz, hz);

        u64 dot  = ffma2(HZ, ZC, ffma2(HY, ZB, fmul2(HX, ZA)));
        u64 smsg = ffma2(g[1], dot, fmul2(g[0], Z0));
        u64 tt   = fmul2(g[3], Z0);
        u64 vx   = ffma2(HX, tt, fmul2(g[2], ZA));
        u64 vy   = ffma2(HY, tt, fmul2(g[2], ZB));
        u64 vz   = ffma2(HZ, tt, fmul2(g[2], ZC));

        float* base = g_accP + (size_t)s * 256 + lane * 8;
        red4(base, smsg, vx);
        red4(base + 4, vy, vz);

        e = en; s = sn; d = dn;
    }
}

// ---------------------------------------------------------------------------
// 5) final: out0 = acc_s @ W_s ; out1[:,i,:] = acc_v_i @ W_v
//    acc is interleaved: (msg m, channel k) -> (k>>1)*8 + m*2 + (k&1)
// ---------------------------------------------------------------------------
__global__ __launch_bounds__(256) void final_kernel(const float* __restrict__ W_s,
                                                    const float* __restrict__ W_v,
                                                    float* __restrict__ out) {
    __shared__ float as[16][256];
    int base = blockIdx.x * 16;
    for (int i = threadIdx.x; i < 16 * 256; i += 256) as[i >> 8][i & 255] = g_accP[(size_t)base * 256 + i];
    __syncthreads();
    int o = threadIdx.x;
    int c = o & 63;
    int m = (o < 64) ? 0 : 1 + ((o - 64) >> 6);
    const float* W = (o < 64) ? W_s : W_v;
    float a[16];
    #pragma unroll
    for (int n = 0; n < 16; n++) a[n] = 0.f;
    for (int k = 0; k < 64; k++) {
        float wv = W[k * 64 + c];
        int idx = (k >> 1) * 8 + m * 2 + (k & 1);
        #pragma unroll
        for (int n = 0; n < 16; n++) a[n] += as[n][idx] * wv;
    }
    if (m == 0) {
        #pragma unroll
        for (int n = 0; n < 16; n++) out[(base + n) * 64 + c] = a[n];
    } else {
        int i = m - 1;
        #pragma unroll
        for (int n = 0; n < 16; n++)
            out[NN * 64 + ((base + n) * 3 + i) * 64 + c] = a[n];
    }
}

// ---------------------------------------------------------------------------
extern "C" void kernel_launch(void* const* d_in, const int* in_sizes, int n_in,
                              void* d_out, int out_size) {
    const int*   src    = (const int*)d_in[0];
    const int*   dst    = (const int*)d_in[1];
    const float* r_ij   = (const float*)d_in[2];
    const float* z_0    = (const float*)d_in[3];
    const float* z_1    = (const float*)d_in[4];
    const float* emb    = (const float*)d_in[5];
    const float* W_enc  = (const float*)d_in[6];
    const float* b_enc  = (const float*)d_in[7];
    const float* W_src  = (const float*)d_in[8];
    const float* b_src  = (const float*)d_in[9];
    const float* W_dst  = (const float*)d_in[10];
    const float* b_dst  = (const float*)d_in[11];
    const float* W_gate = (const float*)d_in[12];
    const float* b_gate = (const float*)d_in[13];
    const float* W_s    = (const float*)d_in[14];
    const float* W_v    = (const float*)d_in[15];
    float* out = (float*)d_out;

    zero_convert<<<2048, 256>>>(z_0, z_1);
    prep_weights<<<137, 256>>>(W_src, W_dst, W_enc, W_gate, b_gate, b_enc, b_src, b_dst);
    node_pre<<<(NN + 31) / 32, 512>>>(emb);
    edge_kernel<<<1184, 256>>>(src, dst, r_ij);
    final_kernel<<<NN / 16, 256>>>(W_s, W_v, out);
}